// round 1
// baseline (speedup 1.0000x reference)
#include <cuda_runtime.h>

// AFT simple attention (causal branch), fp32.
// Shapes: queries/keys/values [N=4, L=8192, H=16, E=64], mask [N, L] (additive).
// out[n,l,h,e] = sigmoid(q) * cumsum_l( exp(k+m) / cumsum_l(exp(k+m)) * v )
// The reference's global-max subtraction cancels exactly in the ratio, so we skip it.
//
// Grid: 128 blocks = (n, h, e-half). Each block scans L=8192 for 32 channels.
// Block: 256 threads = (s: 0..7 subchunks along L) x (c: 0..31 channels).
// Chunked scan: 64 rows/chunk, 8 rows/thread; register-local prefix + smem combine.

static constexpr int N_ = 4, L_ = 8192, H_ = 16, E_ = 64;
static constexpr int CH = 32;            // channels per block
static constexpr int SS = 8;             // subchunks along L
static constexpr int RR = 8;             // rows per thread per chunk
static constexpr int CL = SS * RR;       // 64 rows per chunk
static constexpr int NCHUNK = L_ / CL;   // 128 chunks

__global__ __launch_bounds__(SS * CH)
void aft_scan_kernel(const float* __restrict__ gq,
                     const float* __restrict__ gk,
                     const float* __restrict__ gv,
                     const float* __restrict__ gmask,
                     float* __restrict__ gout)
{
    __shared__ float s_sum[SS][CH];
    __shared__ float s_carryS[CH];
    __shared__ float s_carryA[CH];

    const int b     = blockIdx.x;
    const int ehalf = b & 1;
    const int h     = (b >> 1) & (H_ - 1);
    const int n     = b >> 5;
    const int c     = threadIdx.x & (CH - 1);
    const int s     = threadIdx.x >> 5;

    if (threadIdx.x < CH) { s_carryS[c] = 0.f; s_carryA[c] = 0.f; }
    __syncthreads();

    const int  e        = ehalf * CH + c;
    const long strideL  = (long)H_ * E_;                 // 1024 floats between rows
    const long idx0     = (((long)n * L_) * H_ + h) * E_ + e + (long)(s * RR) * strideL;

    const float* pk = gk + idx0;
    const float* pv = gv + idx0;
    const float* pq = gq + idx0;
    float*       po = gout + idx0;
    const float* pm = gmask + (long)n * L_ + s * RR;

    for (int chunk = 0; chunk < NCHUNK; ++chunk) {
        // ---- front-batched loads (high MLP, streaming hint: data touched once) ----
        float kr[RR], vr[RR], qr[RR], mr[RR];
        #pragma unroll
        for (int r = 0; r < RR; ++r) kr[r] = __ldcs(pk + (long)r * strideL);
        #pragma unroll
        for (int r = 0; r < RR; ++r) vr[r] = __ldcs(pv + (long)r * strideL);
        #pragma unroll
        for (int r = 0; r < RR; ++r) qr[r] = __ldcs(pq + (long)r * strideL);
        #pragma unroll
        for (int r = 0; r < RR; ++r) mr[r] = __ldg(pm + r);   // warp-broadcast

        // ---- phase A: e = exp(k + m), per-channel inclusive prefix S ----
        float er[RR], pre[RR];
        float ls = 0.f;
        #pragma unroll
        for (int r = 0; r < RR; ++r) {
            er[r] = __expf(kr[r] + mr[r]);
            ls += er[r];
            pre[r] = ls;                // inclusive local prefix
        }
        s_sum[s][c] = ls;
        __syncthreads();
        float off = s_carryS[c];
        #pragma unroll
        for (int t = 0; t < SS - 1; ++t) {   // branch-free exclusive combine
            float x = s_sum[t][c];
            off += (t < s) ? x : 0.f;
        }
        __syncthreads();
        if (s == SS - 1) s_carryS[c] = off + ls;  // carry for next chunk

        // ---- phase B: w = e/S, p = w*v, per-channel inclusive prefix ----
        float pa[RR];
        float la = 0.f;
        #pragma unroll
        for (int r = 0; r < RR; ++r) {
            float S = off + pre[r];
            float w = __fdividef(er[r], S);
            la += w * vr[r];
            pa[r] = la;
        }
        s_sum[s][c] = la;
        __syncthreads();
        float offA = s_carryA[c];
        #pragma unroll
        for (int t = 0; t < SS - 1; ++t) {
            float x = s_sum[t][c];
            offA += (t < s) ? x : 0.f;
        }
        __syncthreads();
        if (s == SS - 1) s_carryA[c] = offA + la;

        // ---- epilogue: out = sigmoid(q) * acc ----
        #pragma unroll
        for (int r = 0; r < RR; ++r) {
            float sig = __fdividef(1.f, 1.f + __expf(-qr[r]));
            __stcs(po + (long)r * strideL, sig * (offA + pa[r]));
        }

        pk += (long)CL * strideL;
        pv += (long)CL * strideL;
        pq += (long)CL * strideL;
        po += (long)CL * strideL;
        pm += CL;
    }
}

extern "C" void kernel_launch(void* const* d_in, const int* in_sizes, int n_in,
                              void* d_out, int out_size)
{
    const float* q    = (const float*)d_in[0];
    const float* k    = (const float*)d_in[1];
    const float* v    = (const float*)d_in[2];
    const float* mask = (const float*)d_in[3];
    float* out        = (float*)d_out;

    dim3 grid(N_ * H_ * (E_ / CH));   // 128 blocks
    dim3 block(SS * CH);              // 256 threads
    aft_scan_kernel<<<grid, block>>>(q, k, v, mask, out);
}

// round 4
// speedup vs baseline: 2.0127x; 2.0127x over previous
#include <cuda_runtime.h>

// AFT simple attention (causal branch), fp32.
// Shapes: q/k/v [N=4, L=8192, H=16, E=64], mask [N, L] additive.
// out[n,l,h,e] = sigmoid(q) * cumsum_l( exp(k+m) / cumsum_l(exp(k+m)) * v )
// (reference's global-max subtraction cancels in the ratio; skipped)
//
// R2 kernel, re-submitted after two broker timeouts (unchanged for clean attribution):
//  - grid = 256 blocks = (n, h, e-quarter); block = 256 thr = (s:16 subchunks) x (c:16 ch)
//  - chunk = 128 rows (SS*RR), 64 chunks; double-buffered register prefetch of next
//    chunk's loads issued BEFORE the combine barriers, so DRAM latency overlaps compute.

static constexpr int N_ = 4, L_ = 8192, H_ = 16, E_ = 64;
static constexpr int CH = 16;            // channels per block (E quarter)
static constexpr int SS = 16;            // subchunks along L
static constexpr int RR = 8;             // rows per thread per chunk
static constexpr int CL = SS * RR;       // 128 rows per chunk
static constexpr int NCHUNK = L_ / CL;   // 64 chunks

__global__ __launch_bounds__(SS * CH, 2)
void aft_scan_kernel(const float* __restrict__ gq,
                     const float* __restrict__ gk,
                     const float* __restrict__ gv,
                     const float* __restrict__ gmask,
                     float* __restrict__ gout)
{
    __shared__ float s_sum[SS][CH];
    __shared__ float s_carryS[CH];
    __shared__ float s_carryA[CH];

    const int b  = blockIdx.x;
    const int eq = b & 3;                 // e-quarter
    const int h  = (b >> 2) & (H_ - 1);
    const int n  = b >> 6;
    const int c  = threadIdx.x & (CH - 1);
    const int s  = threadIdx.x >> 4;

    if (threadIdx.x < CH) { s_carryS[c] = 0.f; s_carryA[c] = 0.f; }
    __syncthreads();

    const int  e       = eq * CH + c;
    const long strideL = (long)H_ * E_;   // 1024 floats between rows
    const long idx0    = (((long)n * L_) * H_ + h) * E_ + e + (long)(s * RR) * strideL;

    const float* pk = gk + idx0;
    const float* pv = gv + idx0;
    const float* pq = gq + idx0;
    float*       po = gout + idx0;
    const float* pm = gmask + (long)n * L_ + s * RR;

    // double-buffered register tiles
    float kr[2][RR], vr[2][RR], qr[2][RR], mr[2][RR];

    // preload chunk 0 into buffer 0
    #pragma unroll
    for (int r = 0; r < RR; ++r) kr[0][r] = __ldcs(pk + (long)r * strideL);
    #pragma unroll
    for (int r = 0; r < RR; ++r) vr[0][r] = __ldcs(pv + (long)r * strideL);
    #pragma unroll
    for (int r = 0; r < RR; ++r) qr[0][r] = __ldcs(pq + (long)r * strideL);
    #pragma unroll
    for (int r = 0; r < RR; ++r) mr[0][r] = __ldg(pm + r);

    #pragma unroll 2
    for (int chunk = 0; chunk < NCHUNK; ++chunk) {
        const int cur = chunk & 1;
        const int nxt = cur ^ 1;

        // ---- prefetch next chunk (issued before any barrier; consumed next iter) ----
        if (chunk + 1 < NCHUNK) {
            const long off = (long)(chunk + 1) * CL * strideL;
            const float* nk = pk + off;
            const float* nv = pv + off;
            const float* nq = pq + off;
            const float* nm = pm + (chunk + 1) * CL;
            #pragma unroll
            for (int r = 0; r < RR; ++r) kr[nxt][r] = __ldcs(nk + (long)r * strideL);
            #pragma unroll
            for (int r = 0; r < RR; ++r) vr[nxt][r] = __ldcs(nv + (long)r * strideL);
            #pragma unroll
            for (int r = 0; r < RR; ++r) qr[nxt][r] = __ldcs(nq + (long)r * strideL);
            #pragma unroll
            for (int r = 0; r < RR; ++r) mr[nxt][r] = __ldg(nm + r);
        }

        // ---- phase A: e = exp(k + m), per-channel inclusive local prefix ----
        float er[RR], pre[RR];
        float ls = 0.f;
        #pragma unroll
        for (int r = 0; r < RR; ++r) {
            er[r] = __expf(kr[cur][r] + mr[cur][r]);
            ls += er[r];
            pre[r] = ls;
        }
        s_sum[s][c] = ls;
        __syncthreads();
        float off = s_carryS[c];
        #pragma unroll
        for (int t = 0; t < SS - 1; ++t) {   // branch-free exclusive combine
            float x = s_sum[t][c];
            off += (t < s) ? x : 0.f;
        }
        __syncthreads();
        if (s == SS - 1) s_carryS[c] = off + ls;

        // ---- phase B: w = e/S, p = w*v, per-channel inclusive local prefix ----
        float pa[RR];
        float la = 0.f;
        #pragma unroll
        for (int r = 0; r < RR; ++r) {
            float S = off + pre[r];
            float w = __fdividef(er[r], S);
            la += w * vr[cur][r];
            pa[r] = la;
        }
        s_sum[s][c] = la;
        __syncthreads();
        float offA = s_carryA[c];
        #pragma unroll
        for (int t = 0; t < SS - 1; ++t) {
            float x = s_sum[t][c];
            offA += (t < s) ? x : 0.f;
        }
        __syncthreads();
        if (s == SS - 1) s_carryA[c] = offA + la;

        // ---- epilogue: out = sigmoid(q) * acc ----
        float* o = po + (long)chunk * CL * strideL;
        #pragma unroll
        for (int r = 0; r < RR; ++r) {
            float sig = __fdividef(1.f, 1.f + __expf(-qr[cur][r]));
            __stcs(o + (long)r * strideL, sig * (offA + pa[r]));
        }
    }
}

extern "C" void kernel_launch(void* const* d_in, const int* in_sizes, int n_in,
                              void* d_out, int out_size)
{
    const float* q    = (const float*)d_in[0];
    const float* k    = (const float*)d_in[1];
    const float* v    = (const float*)d_in[2];
    const float* mask = (const float*)d_in[3];
    float* out        = (float*)d_out;

    dim3 grid(N_ * H_ * (E_ / CH));   // 256 blocks
    dim3 block(SS * CH);              // 256 threads
    aft_scan_kernel<<<grid, block>>>(q, k, v, mask, out);
}